// round 8
// baseline (speedup 1.0000x reference)
#include <cuda_runtime.h>
#include <cuda_fp16.h>
#include <cstdint>

// Problem constants
#define B_DIM 2
#define T_DIM 1024
#define H_DIM 32
#define P_DIM 64
#define N_DIM 128
#define BH (B_DIM * H_DIM)
#define Y_SIZE (B_DIM * T_DIM * H_DIM * P_DIM)
#define FS_SIZE (BH * P_DIM * N_DIM)
#define NSPLIT 8

__device__ float g_Acs[BH * T_DIM];
__device__ float g_part[NSPLIT * FS_SIZE];

// ---------------- helpers ----------------
__device__ __forceinline__ uint32_t smem_u32(const void* p) {
    uint32_t a;
    asm("{ .reg .u64 t; cvta.to.shared.u64 t, %1; cvt.u32.u64 %0, t; }" : "=r"(a) : "l"(p));
    return a;
}
__device__ __forceinline__ void ldsm4(uint32_t& r0, uint32_t& r1, uint32_t& r2, uint32_t& r3, uint32_t addr) {
    asm volatile("ldmatrix.sync.aligned.m8n8.x4.shared.b16 {%0,%1,%2,%3}, [%4];"
                 : "=r"(r0), "=r"(r1), "=r"(r2), "=r"(r3) : "r"(addr));
}
__device__ __forceinline__ void mma16816(float* d, uint32_t a0, uint32_t a1, uint32_t a2, uint32_t a3,
                                         uint32_t b0, uint32_t b1) {
    asm volatile("mma.sync.aligned.m16n8k16.row.col.f32.f16.f16.f32 "
                 "{%0,%1,%2,%3}, {%4,%5,%6,%7}, {%8,%9}, {%0,%1,%2,%3};"
                 : "+f"(d[0]), "+f"(d[1]), "+f"(d[2]), "+f"(d[3])
                 : "r"(a0), "r"(a1), "r"(a2), "r"(a3), "r"(b0), "r"(b1));
}
// pack two fp32 -> f16x2 (x in low half)
__device__ __forceinline__ uint32_t pack_h2(float x, float y) {
    uint32_t r;
    asm("cvt.rn.f16x2.f32 %0, %1, %2;" : "=r"(r) : "f"(y), "f"(x));
    return r;
}

// SMEM layout. Pitches keep ldmatrix rows in distinct 16B groups.
#define PCH 272
#define PXH 144
#define O_ECOL 0                              // 2 x 64 floats
#define O_C    1024                           // 64 * PCH = 17408 (fp16 C)
#define O_B    (O_C + 64 * PCH)               // 18432 ; 2 bufs x 17408
#define O_X    (O_B + 2 * 17408)              // 53248 ; 2 bufs x 9216
#define SMEM_BYTES (O_X + 2 * 9216)           // 71680

#define THREADS 256
#define KCH 16    // T / 64

// ---------------------------------------------------------------------------
__global__ void __launch_bounds__(1024) acs_kernel(const float* __restrict__ A) {
    int bh = blockIdx.x;
    int b = bh >> 5, h = bh & 31;
    __shared__ float buf[2][T_DIM];
    int t = threadIdx.x;
    buf[0][t] = A[(size_t)(b * T_DIM + t) * H_DIM + h];
    __syncthreads();
    int src = 0;
    for (int off = 1; off < T_DIM; off <<= 1) {
        float v = buf[src][t];
        if (t >= off) v += buf[src][t - off];
        buf[src ^ 1][t] = v;
        src ^= 1;
        __syncthreads();
    }
    g_Acs[bh * T_DIM + t] = buf[src][t];
}

// ---------------------------------------------------------------------------
// Main kernel: block = (r, bh) with 64 rows, 8 warps (4 row-groups x 2 j-halves).
// 2 CTAs/SM. Single-pass fp16 both stages. Double-buffered B/X tiles.
// ---------------------------------------------------------------------------
__global__ void __launch_bounds__(THREADS, 2)
ssd_mma_kernel(const float* __restrict__ xg, const float* __restrict__ Bg,
               const float* __restrict__ Cg, const float* __restrict__ Lm,
               const float* __restrict__ msfp, float* __restrict__ Yg)
{
    extern __shared__ char smb[];
    float* ecolb = (float*)(smb + O_ECOL);
    const uint32_t sb = smem_u32(smb);

    const int r  = (KCH - 1) - (int)blockIdx.x;   // 15..0, longest first
    const int bh = blockIdx.y;
    const int b = bh >> 5, h = bh & 31;
    const int tid = threadIdx.x;
    const int w = tid >> 5, lane = tid & 31;
    const int wr = w & 3;             // row group (16 rows each)
    const int joff = (w >> 2) * 32;   // j half
    const float msf = *msfp;
    const float* acs = g_Acs + (size_t)bh * T_DIM;
    const int ncols = r + 1;
    const int row0 = r * 64;

    // ---- load + round C (64 x 128) once -> fp16 tile ----
    for (int u = 0; u < 8; ++u) {
        int idx = tid + u * THREADS;
        int row = idx >> 5, q = idx & 31;
        float4 v = *(const float4*)(Cg + ((size_t)((b * T_DIM + row0 + row) * H_DIM) + h) * N_DIM + q * 4);
        *(uint2*)(smb + O_C + row * PCH + q * 8) =
            make_uint2(pack_h2(v.x, v.y), pack_h2(v.z, v.w));
    }

    // lane geometry
    const int g = lane >> 3;
    const int lrow = (g & 1) * 8 + (lane & 7);
    const int lcolB = (g >> 1) * 16;
    const uint32_t aC = sb + O_C + (wr * 16 + lrow) * PCH + lcolB;

    const int ig0 = row0 + wr * 16 + (lane >> 2);
    const int ig1 = ig0 + 8;
    const float av0 = acs[ig0], av1 = acs[ig1];
    const int jmaxRow = row0 + wr * 16 + 15;
    const float* lr0 = Lm + ((size_t)bh * T_DIM + ig0) * T_DIM;
    const float* lr1 = lr0 + 8 * T_DIM;

    float yacc[8][4];
#pragma unroll
    for (int i = 0; i < 8; i++)
#pragma unroll
        for (int e = 0; e < 4; e++) yacc[i][e] = 0.f;

    // ---- staging registers ----
    float4 bR[8], xR[4];
    auto loadBX = [&](int c) {
#pragma unroll
        for (int u = 0; u < 8; ++u) {
            int idx = tid + u * THREADS;
            int row = idx >> 5, q = idx & 31;
            bR[u] = *(const float4*)(Bg + ((size_t)((b * T_DIM + c * 64 + row) * H_DIM) + h) * N_DIM + q * 4);
        }
#pragma unroll
        for (int u = 0; u < 4; ++u) {
            int idx = tid + u * THREADS;
            int j = idx >> 4, q = idx & 15;
            xR[u] = *(const float4*)(xg + ((size_t)((b * T_DIM + c * 64 + j) * H_DIM) + h) * P_DIM + q * 4);
        }
    };
    auto storeBX = [&](int nb) {
        char* bbase = smb + O_B + nb * 17408;
#pragma unroll
        for (int u = 0; u < 8; ++u) {
            int idx = tid + u * THREADS;
            int row = idx >> 5, q = idx & 31;
            *(uint2*)(bbase + row * PCH + q * 8) =
                make_uint2(pack_h2(bR[u].x, bR[u].y), pack_h2(bR[u].z, bR[u].w));
        }
        char* xbase = smb + O_X + nb * 9216;
#pragma unroll
        for (int u = 0; u < 4; ++u) {
            int idx = tid + u * THREADS;
            int j = idx >> 4, q = idx & 15;
            const float* vp = (const float*)&xR[u];
#pragma unroll
            for (int e = 0; e < 4; ++e) {
                int p = 4 * q + e;
                *(__half*)(xbase + p * PXH + j * 2) = __float2half_rn(vp[e]);
            }
        }
    };

    // ---- prologue ----
    loadBX(0);
    float ecv = 0.f;
    if (tid < 64) ecv = __expf(acs[0] - acs[tid]);
    storeBX(0);
    if (tid < 64) ecolb[tid] = ecv;
    __syncthreads();

    for (int c = 0; c < ncols; ++c) {
        const int cur = c & 1;
        const bool more = (c + 1 < ncols);
        if (more) loadBX(c + 1);
        float ecn = 0.f;
        if (more && tid < 64) ecn = __expf(__ldg(acs + (c + 1) * 64) - __ldg(acs + (c + 1) * 64 + tid));

        const bool active = (c * 64 <= jmaxRow);
        if (active) {
            // ---- Lm prefetch ----
            float2 L0[4], L1[4];
            const float* l0p = lr0 + c * 64 + joff;
            const float* l1p = lr1 + c * 64 + joff;
#pragma unroll
            for (int nf = 0; nf < 4; ++nf) {
                int jl = 8 * nf + (lane & 3) * 2;
                L0[nf] = *(const float2*)(l0p + jl);
                L1[nf] = *(const float2*)(l1p + jl);
            }
            const float aj0 = __ldg(acs + c * 64);

            // ---- Stage 1: S(16x32) = C·B^T (single fp16 pass) ----
            float sacc[4][4];
#pragma unroll
            for (int i = 0; i < 4; i++)
#pragma unroll
                for (int e = 0; e < 4; e++) sacc[i][e] = 0.f;

            const uint32_t bBase = sb + O_B + cur * 17408 + (joff + lrow) * PCH + lcolB;
#pragma unroll
            for (int ks = 0; ks < 8; ++ks) {
                uint32_t a0, a1, a2, a3;
                ldsm4(a0, a1, a2, a3, aC + ks * 32);
#pragma unroll
                for (int nf2 = 0; nf2 < 2; ++nf2) {
                    uint32_t b0, b1, b2, b3;
                    ldsm4(b0, b1, b2, b3, bBase + nf2 * (16 * PCH) + ks * 32);
                    mma16816(sacc[2 * nf2],     a0, a1, a2, a3, b0, b2);
                    mma16816(sacc[2 * nf2 + 1], a0, a1, a2, a3, b1, b3);
                }
            }

            // ---- Epilogue: mask + round Ms to fp16 A-frags ----
            const float erow0 = __expf(av0 - aj0);
            const float erow1 = __expf(av1 - aj0);
            const float* ecol = ecolb + cur * 64;
            uint32_t mhi[8];
#pragma unroll
            for (int nf = 0; nf < 4; ++nf) {
                int jl = joff + 8 * nf + (lane & 3) * 2;
                int jgv = c * 64 + jl;
                float2 ec = *(const float2*)(ecol + jl);
                float f00 = (jgv     <= ig0) ? fmaf(msf, L0[nf].x, erow0 * ec.x) : 0.f;
                float f01 = (jgv + 1 <= ig0) ? fmaf(msf, L0[nf].y, erow0 * ec.y) : 0.f;
                float f10 = (jgv     <= ig1) ? fmaf(msf, L1[nf].x, erow1 * ec.x) : 0.f;
                float f11 = (jgv + 1 <= ig1) ? fmaf(msf, L1[nf].y, erow1 * ec.y) : 0.f;
                int ks = nf >> 1, part = nf & 1;
                int i0 = ks * 4 + part * 2;
                mhi[i0]     = pack_h2(sacc[nf][0] * f00, sacc[nf][1] * f01);
                mhi[i0 + 1] = pack_h2(sacc[nf][2] * f10, sacc[nf][3] * f11);
            }

            // ---- Stage 2: Y += Ms·X (single fp16 pass) ----
            const uint32_t xBase = sb + O_X + cur * 9216 + lrow * PXH + joff * 2 + lcolB;
#pragma unroll
            for (int ks = 0; ks < 2; ++ks) {
#pragma unroll
                for (int pf2 = 0; pf2 < 4; ++pf2) {
                    uint32_t b0, b1, b2, b3;
                    ldsm4(b0, b1, b2, b3, xBase + pf2 * (16 * PXH) + ks * 32);
                    mma16816(yacc[2 * pf2],     mhi[4 * ks], mhi[4 * ks + 1], mhi[4 * ks + 2], mhi[4 * ks + 3], b0, b2);
                    mma16816(yacc[2 * pf2 + 1], mhi[4 * ks], mhi[4 * ks + 1], mhi[4 * ks + 2], mhi[4 * ks + 3], b1, b3);
                }
            }
        }

        if (more) {
            storeBX((c + 1) & 1);
            if (tid < 64) ecolb[((c + 1) & 1) * 64 + tid] = ecn;
        }
        __syncthreads();
    }

    // ---- reduce warp pairs (w, w+4) and write Y ----
    float* stag = (float*)(smb + O_B);
    if (w >= 4) {
        float* d = stag + ((w - 4) * 32 + lane) * 32;
#pragma unroll
        for (int i = 0; i < 8; ++i)
#pragma unroll
            for (int e = 0; e < 4; ++e) d[i * 4 + e] = yacc[i][e];
    }
    __syncthreads();
    if (w < 4) {
        const float* s = stag + (w * 32 + lane) * 32;
        float* yr0 = Yg + ((size_t)((b * T_DIM + ig0) * H_DIM) + h) * P_DIM;
        float* yr1 = Yg + ((size_t)((b * T_DIM + ig1) * H_DIM) + h) * P_DIM;
#pragma unroll
        for (int pf = 0; pf < 8; ++pf) {
            int p0 = 8 * pf + (lane & 3) * 2;
            *(float2*)(yr0 + p0) = make_float2(yacc[pf][0] + s[pf * 4 + 0], yacc[pf][1] + s[pf * 4 + 1]);
            *(float2*)(yr1 + p0) = make_float2(yacc[pf][2] + s[pf * 4 + 2], yacc[pf][3] + s[pf * 4 + 3]);
        }
    }
}

// ---------------------------------------------------------------------------
// final_state partials + reduce (fp32, unchanged)
// ---------------------------------------------------------------------------
#define PC 132
#define PX 68
__global__ void __launch_bounds__(256) state_kernel(
    const float* __restrict__ xg, const float* __restrict__ Bg)
{
    int split = blockIdx.x;
    int bh    = blockIdx.y;
    int b = bh >> 5, h = bh & 31;
    const float* acs = g_Acs + (size_t)bh * T_DIM;
    float atot = acs[T_DIM - 1];

    __shared__ float sx[32 * PX];
    __shared__ float sb[32 * PC];
    __shared__ float sd[32];

    int tid = threadIdx.x;
    int i2 = tid >> 4, j2 = tid & 15;
    float acc[4][8];
#pragma unroll
    for (int a = 0; a < 4; a++)
#pragma unroll
        for (int c2 = 0; c2 < 8; c2++) acc[a][c2] = 0.f;

    const int tspan = T_DIM / NSPLIT;
    const int t0base = split * tspan;
    for (int t0 = t0base; t0 < t0base + tspan; t0 += 32) {
        __syncthreads();
        for (int idx = tid; idx < 32 * 16; idx += 256) {
            int row = idx >> 4, q = idx & 15;
            *(float4*)(sx + row * PX + q * 4) =
                *(const float4*)(xg + ((size_t)((b * T_DIM + t0 + row) * H_DIM) + h) * P_DIM + q * 4);
        }
        for (int idx = tid; idx < 32 * 32; idx += 256) {
            int row = idx >> 5, q = idx & 31;
            *(float4*)(sb + row * PC + q * 4) =
                *(const float4*)(Bg + ((size_t)((b * T_DIM + t0 + row) * H_DIM) + h) * N_DIM + q * 4);
        }
        if (tid < 32) sd[tid] = __expf(atot - acs[t0 + tid]);
        __syncthreads();

        for (int tt = 0; tt < 32; ++tt) {
            float d = sd[tt];
            float a0[4], b0[8];
#pragma unroll
            for (int di = 0; di < 4; di++) a0[di] = sx[tt * PX + i2 + 16 * di] * d;
#pragma unroll
            for (int dj = 0; dj < 8; dj++) b0[dj] = sb[tt * PC + j2 + 16 * dj];
#pragma unroll
            for (int di = 0; di < 4; di++)
#pragma unroll
                for (int dj = 0; dj < 8; dj++)
                    acc[di][dj] += a0[di] * b0[dj];
        }
    }

    float* outp = g_part + ((size_t)split * BH + bh) * (P_DIM * N_DIM);
#pragma unroll
    for (int di = 0; di < 4; di++)
#pragma unroll
        for (int dj = 0; dj < 8; dj++)
            outp[(i2 + 16 * di) * N_DIM + (j2 + 16 * dj)] = acc[di][dj];
}

__global__ void reduce_kernel(float* __restrict__ out) {
    int idx = blockIdx.x * 256 + threadIdx.x;
    if (idx < FS_SIZE) {
        float s = 0.f;
#pragma unroll
        for (int sp = 0; sp < NSPLIT; ++sp)
            s += g_part[(size_t)sp * FS_SIZE + idx];
        out[Y_SIZE + idx] = s;
    }
}

// ---------------------------------------------------------------------------
extern "C" void kernel_launch(void* const* d_in, const int* in_sizes, int n_in,
                              void* d_out, int out_size) {
    const float* xg  = (const float*)d_in[0];
    const float* Ag  = (const float*)d_in[1];
    const float* Bg  = (const float*)d_in[2];
    const float* Cg  = (const float*)d_in[3];
    const float* Lm  = (const float*)d_in[4];
    const float* msf = (const float*)d_in[5];
    float* out = (float*)d_out;

    acs_kernel<<<BH, 1024>>>(Ag);

    cudaFuncSetAttribute(ssd_mma_kernel,
                         cudaFuncAttributeMaxDynamicSharedMemorySize, SMEM_BYTES);
    ssd_mma_kernel<<<dim3(KCH, BH), THREADS, SMEM_BYTES>>>(xg, Bg, Cg, Lm, msf, out);

    state_kernel<<<dim3(NSPLIT, BH), 256>>>(xg, Bg);
    reduce_kernel<<<(FS_SIZE + 255) / 256, 256>>>(out);
}